// round 1
// baseline (speedup 1.0000x reference)
#include <cuda_runtime.h>
#include <cstdint>

#define N_WG   512
#define MPAIR  256
#define NCOL   512
#define N_NODE (NCOL * MPAIR)
#define BATCH  8192

// ---------------------------------------------------------------------------
// Packed f32x2 helpers (ptxas never auto-fuses FFMA2; must come from PTX)
// ---------------------------------------------------------------------------
typedef unsigned long long F2;

__device__ __forceinline__ F2 pk(float lo, float hi) {
    F2 r; asm("mov.b64 %0, {%1, %2};" : "=l"(r) : "f"(lo), "f"(hi)); return r;
}
__device__ __forceinline__ void un2(F2 v, float& lo, float& hi) {
    asm("mov.b64 {%0, %1}, %2;" : "=f"(lo), "=f"(hi) : "l"(v));
}
__device__ __forceinline__ F2 splat(float a) { return pk(a, a); }
__device__ __forceinline__ F2 fma2(F2 a, F2 b, F2 c) {
    F2 d; asm("fma.rn.f32x2 %0, %1, %2, %3;" : "=l"(d) : "l"(a), "l"(b), "l"(c)); return d;
}
__device__ __forceinline__ F2 mul2(F2 a, F2 b) {
    F2 d; asm("mul.rn.f32x2 %0, %1, %2;" : "=l"(d) : "l"(a), "l"(b)); return d;
}

__device__ __forceinline__ float2 cmul(float2 a, float2 b) {
    return make_float2(a.x * b.x - a.y * b.y, a.x * b.y + a.y * b.x);
}
__device__ __forceinline__ float2 cadd(float2 a, float2 b) {
    return make_float2(a.x + b.x, a.y + b.y);
}

// ---------------------------------------------------------------------------
// Static scratch (no allocations allowed)
// ---------------------------------------------------------------------------
__device__ float2 g_U00[N_NODE], g_U01[N_NODE], g_U10[N_NODE], g_U11[N_NODE];
// G layout: g_G[j*1024 + m], j = input waveguide (GEMM K-dim), m = output row
// (m < 512: Re A[m][j], m >= 512: Im A[m-512][j])
__device__ float g_G[512 * 1024];

// ---------------------------------------------------------------------------
// Kernel 1: fuse per-node (phase phi, DC_L, phase theta, DC_R) into one 2x2 U.
// Acting convention (matches reference _transform):
//   new_t = U00*vt + U01*vb ; new_b = U10*vt + U11*vb
// ---------------------------------------------------------------------------
__global__ void build_u(const float* __restrict__ th, const float* __restrict__ ph,
                        const float* __restrict__ bse, const float* __restrict__ lse) {
    int idx = blockIdx.x * blockDim.x + threadIdx.x;
    if (idx >= N_NODE) return;
    int c = idx >> 8;
    int p = idx & 255;
    bool msk = ((c & 1) == 0) || (p < MPAIR - 1);

    float2 U00 = {1.f, 0.f}, U01 = {0.f, 0.f}, U10 = {0.f, 0.f}, U11 = {1.f, 0.f};
    if (msk) {
        float theta = th[idx], phi = ph[idx];
        float e0 = bse[2 * idx], e1 = bse[2 * idx + 1];
        float l0 = lse[2 * idx], l1 = lse[2 * idx + 1];
        const float KL = 0.11512925464970229f;  // ln(10)/20
        float ins0 = expf(l0 * KL), ins1 = expf(l1 * KL);
        const float PI4 = 0.7853981633974483f;
        float s0, c0, s1, c1;
        sincosf(PI4 + e0, &s0, &c0);
        sincosf(PI4 + e1, &s1, &c1);
        float2 EL, ET;
        sincosf(phi, &EL.y, &EL.x);
        sincosf(theta, &ET.y, &ET.x);
        // Column matrices in "acting" convention: M = [[T11, T21],[T12, T22]]
        float2 L11 = {ins0 * s0, 0.f}, L12 = {0.f, ins0 * c0}, L21 = {0.f, c0}, L22 = {s0, 0.f};
        float2 R11 = {ins1 * s1, 0.f}, R12 = {0.f, ins1 * c1}, R21 = {0.f, c1}, R22 = {s1, 0.f};
        // M2 = P(theta) * ML * P(phi) = [[L11*EL*ET, L21*ET],[L12*EL, L22]]
        float2 M00 = cmul(L11, cmul(EL, ET));
        float2 M10 = cmul(L12, EL);
        float2 M01 = cmul(L21, ET);
        float2 M11 = L22;
        // U = MR * M2
        U00 = cadd(cmul(R11, M00), cmul(R21, M10));
        U01 = cadd(cmul(R11, M01), cmul(R21, M11));
        U10 = cadd(cmul(R12, M00), cmul(R22, M10));
        U11 = cadd(cmul(R12, M01), cmul(R22, M11));
    }
    g_U00[idx] = U00; g_U01[idx] = U01; g_U10[idx] = U10; g_U11[idx] = U11;
}

// ---------------------------------------------------------------------------
// Kernel 2: build A = mesh * diag(e^{i gamma}) by propagating through columns.
// Thread r (0..255) owns rows (2r, 2r+1) for 4 A-columns (2 f32x2 packs).
// Even mesh columns: local 2x2. Odd: exchange row 2r+2 with neighbor via shfl
// (smem for the 7 warp boundaries).
// ---------------------------------------------------------------------------
__device__ __forceinline__ void apply2(const F2* S, F2& tr, F2& ti, F2& br, F2& bi) {
    // S: s00r,s00i,n00i, s01r,s01i,n01i, s10r,s10i,n10i, s11r,s11i,n11i
    F2 ntr = fma2(S[5],  bi, fma2(S[3], br, fma2(S[2], ti, mul2(S[0], tr))));
    F2 nti = fma2(S[4],  br, fma2(S[3], bi, fma2(S[1], tr, mul2(S[0], ti))));
    F2 nbr = fma2(S[11], bi, fma2(S[9], br, fma2(S[8], ti, mul2(S[6], tr))));
    F2 nbi = fma2(S[10], br, fma2(S[9], bi, fma2(S[7], tr, mul2(S[6], ti))));
    tr = ntr; ti = nti; br = nbr; bi = nbi;
}

__global__ __launch_bounds__(256) void build_A(const float* __restrict__ gammas) {
    int r  = threadIdx.x;          // pair index = row group (2r, 2r+1)
    int jb = blockIdx.x * 4;       // 4 A-columns per thread
    int i0 = 2 * r, i1 = 2 * r + 1;
    int lane = r & 31, w = r >> 5;

    float sg0, cg0, sg1, cg1;
    sincosf(gammas[i0], &sg0, &cg0);
    sincosf(gammas[i1], &sg1, &cg1);

    F2 are[2], aim[2], bre[2], bim[2];
#pragma unroll
    for (int k = 0; k < 2; k++) {
        int j0 = jb + 2 * k, j1 = j0 + 1;
        are[k] = pk(i0 == j0 ? cg0 : 0.f, i0 == j1 ? cg0 : 0.f);
        aim[k] = pk(i0 == j0 ? sg0 : 0.f, i0 == j1 ? sg0 : 0.f);
        bre[k] = pk(i1 == j0 ? cg1 : 0.f, i1 == j1 ? cg1 : 0.f);
        bim[k] = pk(i1 == j0 ? sg1 : 0.f, i1 == j1 ? sg1 : 0.f);
    }

    __shared__ F2 sEA[8][4];
    __shared__ F2 sEB[8][4];

    // prefetch column 0 coefficients
    float2 u00 = g_U00[r], u01 = g_U01[r], u10 = g_U10[r], u11 = g_U11[r];

    for (int c = 0; c < NCOL; c++) {
        // prefetch next column's U while computing this one (hide L2 latency)
        float2 p00, p01, p10, p11;
        if (c + 1 < NCOL) {
            int nidx = ((c + 1) << 8) + r;
            p00 = g_U00[nidx]; p01 = g_U01[nidx]; p10 = g_U10[nidx]; p11 = g_U11[nidx];
        }
        F2 S[12] = {
            splat(u00.x), splat(u00.y), splat(-u00.y),
            splat(u01.x), splat(u01.y), splat(-u01.y),
            splat(u10.x), splat(u10.y), splat(-u10.y),
            splat(u11.x), splat(u11.y), splat(-u11.y)
        };
        if ((c & 1) == 0) {
#pragma unroll
            for (int k = 0; k < 2; k++)
                apply2(S, are[k], aim[k], bre[k], bim[k]);
        } else {
            // pair p=r couples (row 2r+1 = my b, row 2r+2 = neighbor's a)
            F2 nar[2], nai[2];
#pragma unroll
            for (int k = 0; k < 2; k++) {
                nar[k] = __shfl_down_sync(0xffffffffu, are[k], 1);
                nai[k] = __shfl_down_sync(0xffffffffu, aim[k], 1);
            }
            if (lane == 0 && r > 0) {
                sEA[w][0] = are[0]; sEA[w][1] = are[1];
                sEA[w][2] = aim[0]; sEA[w][3] = aim[1];
            }
            __syncthreads();
            if (lane == 31 && r < 255) {
                nar[0] = sEA[w + 1][0]; nar[1] = sEA[w + 1][1];
                nai[0] = sEA[w + 1][2]; nai[1] = sEA[w + 1][3];
            }
            if (r < 255) {
#pragma unroll
                for (int k = 0; k < 2; k++)
                    apply2(S, bre[k], bim[k], nar[k], nai[k]);
            }
            // return updated bottom row (2r+2) to thread r+1's 'a'
            F2 up0 = __shfl_up_sync(0xffffffffu, nar[0], 1);
            F2 up1 = __shfl_up_sync(0xffffffffu, nar[1], 1);
            F2 up2 = __shfl_up_sync(0xffffffffu, nai[0], 1);
            F2 up3 = __shfl_up_sync(0xffffffffu, nai[1], 1);
            if (lane == 31 && r < 255) {
                sEB[w + 1][0] = nar[0]; sEB[w + 1][1] = nar[1];
                sEB[w + 1][2] = nai[0]; sEB[w + 1][3] = nai[1];
            }
            __syncthreads();
            if (r > 0) {
                if (lane == 0) {
                    are[0] = sEB[w][0]; are[1] = sEB[w][1];
                    aim[0] = sEB[w][2]; aim[1] = sEB[w][3];
                } else {
                    are[0] = up0; are[1] = up1; aim[0] = up2; aim[1] = up3;
                }
            }
        }
        u00 = p00; u01 = p01; u10 = p10; u11 = p11;
    }

    // write out G (k-major: g_G[j*1024 + m])
#pragma unroll
    for (int k = 0; k < 2; k++) {
        int j0 = jb + 2 * k, j1 = j0 + 1;
        float x, y;
        un2(are[k], x, y); g_G[j0 * 1024 + i0] = x;       g_G[j1 * 1024 + i0] = y;
        un2(aim[k], x, y); g_G[j0 * 1024 + 512 + i0] = x; g_G[j1 * 1024 + 512 + i0] = y;
        un2(bre[k], x, y); g_G[j0 * 1024 + i1] = x;       g_G[j1 * 1024 + i1] = y;
        un2(bim[k], x, y); g_G[j0 * 1024 + 512 + i1] = x; g_G[j1 * 1024 + 512 + i1] = y;
    }
}

// ---------------------------------------------------------------------------
// Kernel 3: out[1024, 8192] = G^T-layout GEMM:  out[m,n] = sum_j g_G[j*1024+m] * x[j*8192+n]
// 128x128 CTA tile, BK=16, 256 threads, 8x8 per-thread (f32x2 along N),
// cp.async double-buffered.
// ---------------------------------------------------------------------------
__global__ __launch_bounds__(256, 2) void gemm_kernel(const float* __restrict__ X,
                                                      float* __restrict__ out) {
    __shared__ __align__(16) float sG[2][16][132];
    __shared__ __align__(16) float sX[2][16][128];

    int tid = threadIdx.x;
    int bn = blockIdx.x * 128;
    int bm = blockIdx.y * 128;
    int tx = tid & 15, ty = tid >> 4;
    int m0 = ty * 8, n0 = tx * 8;
    int lr = tid >> 5;   // 0..7
    int lc = tid & 31;   // 0..31

    F2 acc[8][4];
#pragma unroll
    for (int i = 0; i < 8; i++)
#pragma unroll
        for (int j = 0; j < 4; j++) acc[i][j] = 0ull;

    auto issue = [&](int kt, int buf) {
        int k0 = kt * 16;
#pragma unroll
        for (int h = 0; h < 2; h++) {
            int kr = lr + h * 8;
            const float* srcG = g_G + (k0 + kr) * 1024 + bm + lc * 4;
            unsigned dG = (unsigned)__cvta_generic_to_shared(&sG[buf][kr][lc * 4]);
            asm volatile("cp.async.cg.shared.global [%0], [%1], 16;" :: "r"(dG), "l"(srcG));
            const float* srcX = X + (k0 + kr) * 8192 + bn + lc * 4;
            unsigned dX = (unsigned)__cvta_generic_to_shared(&sX[buf][kr][lc * 4]);
            asm volatile("cp.async.cg.shared.global [%0], [%1], 16;" :: "r"(dX), "l"(srcX));
        }
        asm volatile("cp.async.commit_group;" ::: "memory");
    };

    issue(0, 0);
#pragma unroll 1
    for (int kt = 0; kt < 32; ++kt) {
        int buf = kt & 1;
        if (kt < 31) {
            issue(kt + 1, buf ^ 1);
            asm volatile("cp.async.wait_group 1;" ::: "memory");
        } else {
            asm volatile("cp.async.wait_group 0;" ::: "memory");
        }
        __syncthreads();
#pragma unroll
        for (int k = 0; k < 16; k++) {
            float4 a0 = *(const float4*)&sG[buf][k][m0];
            float4 a1 = *(const float4*)&sG[buf][k][m0 + 4];
            float4 b0 = *(const float4*)&sX[buf][k][n0];
            float4 b1 = *(const float4*)&sX[buf][k][n0 + 4];
            F2 bp[4] = { pk(b0.x, b0.y), pk(b0.z, b0.w), pk(b1.x, b1.y), pk(b1.z, b1.w) };
            float av[8] = { a0.x, a0.y, a0.z, a0.w, a1.x, a1.y, a1.z, a1.w };
#pragma unroll
            for (int i = 0; i < 8; i++) {
                F2 as = splat(av[i]);
#pragma unroll
                for (int j = 0; j < 4; j++) acc[i][j] = fma2(as, bp[j], acc[i][j]);
            }
        }
        __syncthreads();
    }

    // epilogue: coalesced float4 stores
#pragma unroll
    for (int i = 0; i < 8; i++) {
        float* o = out + (size_t)(bm + m0 + i) * 8192 + bn + n0;
        float4 v0, v1;
        un2(acc[i][0], v0.x, v0.y); un2(acc[i][1], v0.z, v0.w);
        un2(acc[i][2], v1.x, v1.y); un2(acc[i][3], v1.z, v1.w);
        *(float4*)o = v0;
        *(float4*)(o + 4) = v1;
    }
}

// ---------------------------------------------------------------------------
// Launch
// ---------------------------------------------------------------------------
extern "C" void kernel_launch(void* const* d_in, const int* in_sizes, int n_in,
                              void* d_out, int out_size) {
    const float* x      = (const float*)d_in[0];
    const float* thetas = (const float*)d_in[1];
    const float* phis   = (const float*)d_in[2];
    const float* gammas = (const float*)d_in[3];
    const float* bse    = (const float*)d_in[4];
    const float* lse    = (const float*)d_in[5];
    (void)in_sizes; (void)n_in; (void)out_size;

    build_u<<<N_NODE / 256, 256>>>(thetas, phis, bse, lse);
    build_A<<<128, 256>>>(gammas);
    gemm_kernel<<<dim3(64, 8), 256>>>(x, (float*)d_out);
}

// round 3
// speedup vs baseline: 1.4393x; 1.4393x over previous
#include <cuda_runtime.h>
#include <cuda_bf16.h>
#include <cstdint>

#define N_WG   512
#define MPAIR  256
#define NCOL   512
#define N_NODE (NCOL * MPAIR)
#define BATCH  8192

// ===========================================================================
// Packed f32x2 helpers
// ===========================================================================
typedef unsigned long long F2;
__device__ __forceinline__ F2 pk(float lo, float hi) {
    F2 r; asm("mov.b64 %0, {%1, %2};" : "=l"(r) : "f"(lo), "f"(hi)); return r;
}
__device__ __forceinline__ void un2(F2 v, float& lo, float& hi) {
    asm("mov.b64 {%0, %1}, %2;" : "=f"(lo), "=f"(hi) : "l"(v));
}
__device__ __forceinline__ F2 splat(float a) { return pk(a, a); }
__device__ __forceinline__ F2 fma2(F2 a, F2 b, F2 c) {
    F2 d; asm("fma.rn.f32x2 %0, %1, %2, %3;" : "=l"(d) : "l"(a), "l"(b), "l"(c)); return d;
}
__device__ __forceinline__ F2 mul2(F2 a, F2 b) {
    F2 d; asm("mul.rn.f32x2 %0, %1, %2;" : "=l"(d) : "l"(a), "l"(b)); return d;
}
__device__ __forceinline__ float2 cmul(float2 a, float2 b) {
    return make_float2(a.x * b.x - a.y * b.y, a.x * b.y + a.y * b.x);
}
__device__ __forceinline__ float2 cadd(float2 a, float2 b) {
    return make_float2(a.x + b.x, a.y + b.y);
}
__device__ __forceinline__ uint32_t smem_u32(const void* p) {
    uint32_t a;
    asm("{ .reg .u64 t; cvta.to.shared.u64 t, %1; cvt.u32.u64 %0, t; }" : "=r"(a) : "l"(p));
    return a;
}

// ===========================================================================
// Static scratch
// ===========================================================================
__device__ float2 g_U00[N_NODE], g_U01[N_NODE], g_U10[N_NODE], g_U11[N_NODE];
// A matrix, m-major (row m = 0..1023, k contiguous), bf16 hi/lo split
__device__ __align__(16) __nv_bfloat16 g_Gh[1024 * 512];
__device__ __align__(16) __nv_bfloat16 g_Gl[1024 * 512];
// X, [k][n] layout (n contiguous), bf16 hi/lo split
__device__ __align__(16) __nv_bfloat16 g_Xh[512 * 8192];
__device__ __align__(16) __nv_bfloat16 g_Xl[512 * 8192];

// ===========================================================================
// Kernel 1: fuse per-node (phi, DC_L, theta, DC_R) into one 2x2 U.
// ===========================================================================
__global__ void build_u(const float* __restrict__ th, const float* __restrict__ ph,
                        const float* __restrict__ bse, const float* __restrict__ lse) {
    int idx = blockIdx.x * blockDim.x + threadIdx.x;
    if (idx >= N_NODE) return;
    int c = idx >> 8;
    int p = idx & 255;
    bool msk = ((c & 1) == 0) || (p < MPAIR - 1);

    float2 U00 = {1.f, 0.f}, U01 = {0.f, 0.f}, U10 = {0.f, 0.f}, U11 = {1.f, 0.f};
    if (msk) {
        float theta = th[idx], phi = ph[idx];
        float e0 = bse[2 * idx], e1 = bse[2 * idx + 1];
        float l0 = lse[2 * idx], l1 = lse[2 * idx + 1];
        const float KL = 0.11512925464970229f;  // ln(10)/20
        float ins0 = expf(l0 * KL), ins1 = expf(l1 * KL);
        const float PI4 = 0.7853981633974483f;
        float s0, c0, s1, c1;
        sincosf(PI4 + e0, &s0, &c0);
        sincosf(PI4 + e1, &s1, &c1);
        float2 EL, ET;
        sincosf(phi, &EL.y, &EL.x);
        sincosf(theta, &ET.y, &ET.x);
        float2 L11 = {ins0 * s0, 0.f}, L12 = {0.f, ins0 * c0}, L21 = {0.f, c0}, L22 = {s0, 0.f};
        float2 R11 = {ins1 * s1, 0.f}, R12 = {0.f, ins1 * c1}, R21 = {0.f, c1}, R22 = {s1, 0.f};
        float2 M00 = cmul(L11, cmul(EL, ET));
        float2 M10 = cmul(L12, EL);
        float2 M01 = cmul(L21, ET);
        float2 M11 = L22;
        U00 = cadd(cmul(R11, M00), cmul(R21, M10));
        U01 = cadd(cmul(R11, M01), cmul(R21, M11));
        U10 = cadd(cmul(R12, M00), cmul(R22, M10));
        U11 = cadd(cmul(R12, M01), cmul(R22, M11));
    }
    g_U00[idx] = U00; g_U01[idx] = U01; g_U10[idx] = U10; g_U11[idx] = U11;
}

// ===========================================================================
// Kernel 2: propagate identity*diag(e^{i gamma}) through mesh -> A, emit bf16
// hi/lo split in m-major layout.
// ===========================================================================
__device__ __forceinline__ void apply2(const F2* S, F2& tr, F2& ti, F2& br, F2& bi) {
    F2 ntr = fma2(S[5],  bi, fma2(S[3], br, fma2(S[2], ti, mul2(S[0], tr))));
    F2 nti = fma2(S[4],  br, fma2(S[3], bi, fma2(S[1], tr, mul2(S[0], ti))));
    F2 nbr = fma2(S[11], bi, fma2(S[9], br, fma2(S[8], ti, mul2(S[6], tr))));
    F2 nbi = fma2(S[10], br, fma2(S[9], bi, fma2(S[7], tr, mul2(S[6], ti))));
    tr = ntr; ti = nti; br = nbr; bi = nbi;
}

__device__ __forceinline__ void store_split(int row, int col, float a, float b) {
    __nv_bfloat16 ha = __float2bfloat16(a), hb = __float2bfloat16(b);
    __nv_bfloat16 la = __float2bfloat16(a - __bfloat162float(ha));
    __nv_bfloat16 lb = __float2bfloat16(b - __bfloat162float(hb));
    __nv_bfloat162 h; h.x = ha; h.y = hb;
    __nv_bfloat162 l; l.x = la; l.y = lb;
    *reinterpret_cast<__nv_bfloat162*>(&g_Gh[(size_t)row * 512 + col]) = h;
    *reinterpret_cast<__nv_bfloat162*>(&g_Gl[(size_t)row * 512 + col]) = l;
}

__global__ __launch_bounds__(256) void build_A(const float* __restrict__ gammas) {
    int r  = threadIdx.x;
    int jb = blockIdx.x * 4;
    int i0 = 2 * r, i1 = 2 * r + 1;
    int lane = r & 31, w = r >> 5;

    float sg0, cg0, sg1, cg1;
    sincosf(gammas[i0], &sg0, &cg0);
    sincosf(gammas[i1], &sg1, &cg1);

    F2 are[2], aim[2], bre[2], bim[2];
#pragma unroll
    for (int k = 0; k < 2; k++) {
        int j0 = jb + 2 * k, j1 = j0 + 1;
        are[k] = pk(i0 == j0 ? cg0 : 0.f, i0 == j1 ? cg0 : 0.f);
        aim[k] = pk(i0 == j0 ? sg0 : 0.f, i0 == j1 ? sg0 : 0.f);
        bre[k] = pk(i1 == j0 ? cg1 : 0.f, i1 == j1 ? cg1 : 0.f);
        bim[k] = pk(i1 == j0 ? sg1 : 0.f, i1 == j1 ? sg1 : 0.f);
    }

    __shared__ F2 sEA[8][4];
    __shared__ F2 sEB[8][4];

    float2 u00 = g_U00[r], u01 = g_U01[r], u10 = g_U10[r], u11 = g_U11[r];

    for (int c = 0; c < NCOL; c++) {
        float2 p00, p01, p10, p11;
        if (c + 1 < NCOL) {
            int nidx = ((c + 1) << 8) + r;
            p00 = g_U00[nidx]; p01 = g_U01[nidx]; p10 = g_U10[nidx]; p11 = g_U11[nidx];
        }
        F2 S[12] = {
            splat(u00.x), splat(u00.y), splat(-u00.y),
            splat(u01.x), splat(u01.y), splat(-u01.y),
            splat(u10.x), splat(u10.y), splat(-u10.y),
            splat(u11.x), splat(u11.y), splat(-u11.y)
        };
        if ((c & 1) == 0) {
#pragma unroll
            for (int k = 0; k < 2; k++)
                apply2(S, are[k], aim[k], bre[k], bim[k]);
        } else {
            F2 nar[2], nai[2];
#pragma unroll
            for (int k = 0; k < 2; k++) {
                nar[k] = __shfl_down_sync(0xffffffffu, are[k], 1);
                nai[k] = __shfl_down_sync(0xffffffffu, aim[k], 1);
            }
            if (lane == 0 && r > 0) {
                sEA[w][0] = are[0]; sEA[w][1] = are[1];
                sEA[w][2] = aim[0]; sEA[w][3] = aim[1];
            }
            __syncthreads();
            if (lane == 31 && r < 255) {
                nar[0] = sEA[w + 1][0]; nar[1] = sEA[w + 1][1];
                nai[0] = sEA[w + 1][2]; nai[1] = sEA[w + 1][3];
            }
            if (r < 255) {
#pragma unroll
                for (int k = 0; k < 2; k++)
                    apply2(S, bre[k], bim[k], nar[k], nai[k]);
            }
            F2 up0 = __shfl_up_sync(0xffffffffu, nar[0], 1);
            F2 up1 = __shfl_up_sync(0xffffffffu, nar[1], 1);
            F2 up2 = __shfl_up_sync(0xffffffffu, nai[0], 1);
            F2 up3 = __shfl_up_sync(0xffffffffu, nai[1], 1);
            if (lane == 31 && r < 255) {
                sEB[w + 1][0] = nar[0]; sEB[w + 1][1] = nar[1];
                sEB[w + 1][2] = nai[0]; sEB[w + 1][3] = nai[1];
            }
            __syncthreads();
            if (r > 0) {
                if (lane == 0) {
                    are[0] = sEB[w][0]; are[1] = sEB[w][1];
                    aim[0] = sEB[w][2]; aim[1] = sEB[w][3];
                } else {
                    are[0] = up0; are[1] = up1; aim[0] = up2; aim[1] = up3;
                }
            }
        }
        u00 = p00; u01 = p01; u10 = p10; u11 = p11;
    }

    // emit bf16 hi/lo, m-major: rows [0,512)=Re, [512,1024)=Im
#pragma unroll
    for (int k = 0; k < 2; k++) {
        int j0 = jb + 2 * k;
        float x, y;
        un2(are[k], x, y); store_split(i0,       j0, x, y);
        un2(aim[k], x, y); store_split(512 + i0, j0, x, y);
        un2(bre[k], x, y); store_split(i1,       j0, x, y);
        un2(bim[k], x, y); store_split(512 + i1, j0, x, y);
    }
}

// ===========================================================================
// Kernel 3: convert X fp32 -> bf16 hi/lo
// ===========================================================================
__global__ __launch_bounds__(256) void convert_x(const float4* __restrict__ X4) {
    int i = blockIdx.x * 256 + threadIdx.x;
    float4 v = X4[i];
    __nv_bfloat162 h0, h1, l0, l1;
    h0.x = __float2bfloat16(v.x); h0.y = __float2bfloat16(v.y);
    h1.x = __float2bfloat16(v.z); h1.y = __float2bfloat16(v.w);
    l0.x = __float2bfloat16(v.x - __bfloat162float(h0.x));
    l0.y = __float2bfloat16(v.y - __bfloat162float(h0.y));
    l1.x = __float2bfloat16(v.z - __bfloat162float(h1.x));
    l1.y = __float2bfloat16(v.w - __bfloat162float(h1.y));
    __nv_bfloat162* Xh2 = reinterpret_cast<__nv_bfloat162*>(g_Xh);
    __nv_bfloat162* Xl2 = reinterpret_cast<__nv_bfloat162*>(g_Xl);
    Xh2[2 * i] = h0; Xh2[2 * i + 1] = h1;
    Xl2[2 * i] = l0; Xl2[2 * i + 1] = l1;
}

// ===========================================================================
// Kernel 4: mma.sync bf16 GEMM (base-ISA; tcgen05 rejected by harness ptxas).
// out[1024][8192] = Gh@Xh + Gh@Xl + Gl@Xh, fp32 accum.
// CTA 128x128, BK=32, 3-stage cp.async pipeline, 8 warps (32x64 each).
// SMEM swizzles (conflict-free, verified):
//   A[row][kc] : off = row*64  + ((kc ^ ((row>>1)&3)) << 4)   (kc = k/8, 0..3)
//   B[k][nch]  : off = k*256   + ((nch ^ (k&7))       << 4)   (nch = n/8, 0..15)
// ===========================================================================
__device__ __forceinline__ void ldmx4(uint32_t* r, uint32_t addr) {
    asm volatile("ldmatrix.sync.aligned.m8n8.x4.shared.b16 {%0,%1,%2,%3}, [%4];"
                 : "=r"(r[0]), "=r"(r[1]), "=r"(r[2]), "=r"(r[3]) : "r"(addr));
}
__device__ __forceinline__ void ldmx4t(uint32_t* r, uint32_t addr) {
    asm volatile("ldmatrix.sync.aligned.m8n8.x4.trans.shared.b16 {%0,%1,%2,%3}, [%4];"
                 : "=r"(r[0]), "=r"(r[1]), "=r"(r[2]), "=r"(r[3]) : "r"(addr));
}
__device__ __forceinline__ void mma_bf16(float* c, const uint32_t* a, uint32_t b0, uint32_t b1) {
    asm volatile("mma.sync.aligned.m16n8k16.row.col.f32.bf16.bf16.f32 "
                 "{%0,%1,%2,%3}, {%4,%5,%6,%7}, {%8,%9}, {%0,%1,%2,%3};"
                 : "+f"(c[0]), "+f"(c[1]), "+f"(c[2]), "+f"(c[3])
                 : "r"(a[0]), "r"(a[1]), "r"(a[2]), "r"(a[3]), "r"(b0), "r"(b1));
}

__global__ __launch_bounds__(256, 2) void mma_gemm(float* __restrict__ out) {
    __shared__ __align__(1024) char raw[3 * 16384];   // 3 stages x (A 8KB + B 8KB)
    uint32_t sbase = smem_u32(raw);

    int tid = threadIdx.x;
    int lane = tid & 31, wid = tid >> 5;
    int wm = wid & 3, wn = wid >> 2;               // warp tile: M 32 x N 64
    int bm = blockIdx.y * 128, bn = blockIdx.x * 128;

    // ---- loader lambda ----
    auto issue = [&](int st, int buf) {
        int p = st >> 4;
        int kblk = (st & 15) << 5;
        const __nv_bfloat16* Ap = (p == 2) ? g_Gl : g_Gh;
        const __nv_bfloat16* Bp = (p == 1) ? g_Xl : g_Xh;
        uint32_t base = sbase + buf * 16384;
#pragma unroll
        for (int h = 0; h < 2; h++) {
            int cA = tid + h * 256;
            int row = cA >> 2, kc = cA & 3;
            uint32_t dA = base + row * 64 + ((kc ^ ((row >> 1) & 3)) << 4);
            const __nv_bfloat16* sA = Ap + (size_t)(bm + row) * 512 + kblk + kc * 8;
            asm volatile("cp.async.cg.shared.global [%0], [%1], 16;" :: "r"(dA), "l"(sA));
            int cB = tid + h * 256;
            int k = cB >> 4, nch = cB & 15;
            uint32_t dB = base + 8192 + k * 256 + ((nch ^ (k & 7)) << 4);
            const __nv_bfloat16* sB = Bp + (size_t)(kblk + k) * 8192 + bn + nch * 8;
            asm volatile("cp.async.cg.shared.global [%0], [%1], 16;" :: "r"(dB), "l"(sB));
        }
        asm volatile("cp.async.commit_group;" ::: "memory");
    };

    // ---- per-lane fragment base addresses ----
    int grp = lane >> 3, lrow = lane & 7;
    int g1 = grp & 1, g2 = grp >> 1;
    // A: row within tile for mt=0; mt=1 adds 16*64 bytes
    int arow = wm * 32 + g1 * 8 + lrow;
    uint32_t aBase = arow * 64 + ((g2 ^ (lrow >> 1)) << 4);   // + buf base; s: ^ (s<<5)
    // B: k row + n-chunk base (j2=0); j2: ^ (j2<<5); s: + (s<<12)
    int bk = g1 * 8 + lrow;
    uint32_t bBase = 8192 + bk * 256 + wn * 128 + ((g2 ^ lrow) << 4);

    float acc[2][8][4];
#pragma unroll
    for (int mt = 0; mt < 2; mt++)
#pragma unroll
        for (int nj = 0; nj < 8; nj++)
#pragma unroll
            for (int q = 0; q < 4; q++) acc[mt][nj][q] = 0.f;

    issue(0, 0);
    issue(1, 1);

#pragma unroll 1
    for (int st = 0; st < 48; st++) {
        int buf = st % 3;
        if (st < 47) asm volatile("cp.async.wait_group 1;" ::: "memory");
        else         asm volatile("cp.async.wait_group 0;" ::: "memory");
        __syncthreads();
        if (st + 2 < 48) issue(st + 2, (st + 2) % 3);

        uint32_t stage = sbase + buf * 16384;
#pragma unroll
        for (int s = 0; s < 2; s++) {
            uint32_t a[2][4];
            ldmx4(a[0], (stage + aBase) ^ (s << 5));
            ldmx4(a[1], (stage + aBase + 16 * 64) ^ (s << 5));
#pragma unroll
            for (int j2 = 0; j2 < 4; j2++) {
                uint32_t b[4];
                ldmx4t(b, (stage + bBase + (s << 12)) ^ (j2 << 5));
#pragma unroll
                for (int mt = 0; mt < 2; mt++) {
                    mma_bf16(acc[mt][2 * j2],     a[mt], b[0], b[1]);
                    mma_bf16(acc[mt][2 * j2 + 1], a[mt], b[2], b[3]);
                }
            }
        }
    }

    // ---- epilogue ----
    int mrow = bm + wm * 32 + (lane >> 2);
    int ncol = bn + wn * 64 + (lane & 3) * 2;
#pragma unroll
    for (int mt = 0; mt < 2; mt++) {
#pragma unroll
        for (int nj = 0; nj < 8; nj++) {
            float* o = out + (size_t)(mrow + mt * 16) * 8192 + ncol + nj * 8;
            *reinterpret_cast<float2*>(o)             = make_float2(acc[mt][nj][0], acc[mt][nj][1]);
            *reinterpret_cast<float2*>(o + 8 * 8192)  = make_float2(acc[mt][nj][2], acc[mt][nj][3]);
        }
    }
}

// ===========================================================================
// Launch
// ===========================================================================
extern "C" void kernel_launch(void* const* d_in, const int* in_sizes, int n_in,
                              void* d_out, int out_size) {
    const float* x      = (const float*)d_in[0];
    const float* thetas = (const float*)d_in[1];
    const float* phis   = (const float*)d_in[2];
    const float* gammas = (const float*)d_in[3];
    const float* bse    = (const float*)d_in[4];
    const float* lse    = (const float*)d_in[5];
    (void)in_sizes; (void)n_in; (void)out_size;

    convert_x<<<4096, 256>>>((const float4*)x);
    build_u<<<N_NODE / 256, 256>>>(thetas, phis, bse, lse);
    build_A<<<128, 256>>>(gammas);
    mma_gemm<<<dim3(64, 8), 256>>>((float*)d_out);
}